// round 2
// baseline (speedup 1.0000x reference)
#include <cuda_runtime.h>

// Fixed problem shape (PANUMPooling_8787503088315)
#define NB   8        // graphs
#define NPG  2048     // nodes per graph
#define KP   1024     // kept per graph
#define FD   128      // feature dim
#define NTOT (NB * NPG)   // 16384 total nodes
#define NK   (NB * KP)    // 8192 kept nodes

// Scratch (device globals: no allocation allowed)
__device__ int   g_perm[NK];
__device__ float g_score[NK];
__device__ int   g_nodemap[NTOT];

// ---------------------------------------------------------------------------
// Kernel 1: per-graph score + stable top-K (bitonic sort of (score,idx) keys)
// One block per graph, 1024 threads, 2048 keys in SMEM.
// Sort key: 64-bit = [monotonic(float diag) : 32][ (NPG-1-idx) : 32 ]
// Descending sort => higher score first; on equal score, lower idx first
// (matches stable argsort(-score)). Sorting by raw diag is order-equivalent
// to sorting by tanh(diag) (monotone).
//
// Barrier optimization: with i = ((tid&~(j-1))<<1)|(tid&(j-1)), all stages
// with j <= 32 operate strictly inside the 64-element block [64w, 64w+64)
// owned by warp w, so they need only __syncwarp(). Only j > 32 stages are
// cross-warp (15 of 66 stages).
// ---------------------------------------------------------------------------
__global__ __launch_bounds__(1024, 1)
void topk_kernel(const float* __restrict__ UM, float* __restrict__ out,
                 int offBatch, int offPerm, int offScore)
{
    __shared__ unsigned long long skey[NPG];
    __shared__ float sdiag[NPG];

    const int g    = blockIdx.x;
    const int tid  = threadIdx.x;
    const int base = g * NPG;

    // Load diagonal, build keys, init node_map (this block owns its graph's range)
    #pragma unroll
    for (int i = tid; i < NPG; i += 1024) {
        const int node = base + i;
        const float d  = UM[(size_t)node * NTOT + node];
        sdiag[i] = d;
        unsigned int bits = __float_as_uint(d);
        unsigned int mono = (bits & 0x80000000u) ? ~bits : (bits | 0x80000000u);
        skey[i] = ((unsigned long long)mono << 32) | (unsigned int)(NPG - 1 - i);
        g_nodemap[node] = -1;
    }
    __syncthreads();

    // Bitonic sort, descending.
    for (int k = 2; k <= NPG; k <<= 1) {
        // Cross-warp stages (j > 32): full barrier after each.
        for (int j = k >> 1; j > 32; j >>= 1) {
            const int i = ((tid & ~(j - 1)) << 1) | (tid & (j - 1));
            const int p = i | j;
            const unsigned long long a = skey[i];
            const unsigned long long b = skey[p];
            const bool bigFirst = ((i & k) == 0);
            if (bigFirst ? (a < b) : (a > b)) { skey[i] = b; skey[p] = a; }
            __syncthreads();
        }
        // Warp-local stages (j <= 32): elements [64w, 64w+64) touched only by warp w.
        for (int j = (k >> 1 > 32) ? 32 : (k >> 1); j > 0; j >>= 1) {
            const int i = ((tid & ~(j - 1)) << 1) | (tid & (j - 1));
            const int p = i | j;
            const unsigned long long a = skey[i];
            const unsigned long long b = skey[p];
            const bool bigFirst = ((i & k) == 0);
            if (bigFirst ? (a < b) : (a > b)) { skey[i] = b; skey[p] = a; }
            __syncwarp();
        }
        __syncthreads();  // publish warp-local results before next k's cross-warp stage
    }

    // Emit top-K: perm, score, node_map, plus batch/perm/score output sections.
    if (tid < KP) {
        const unsigned long long key = skey[tid];
        const int local = NPG - 1 - (int)(key & 0xFFFFFFFFu);
        const int node  = base + local;
        const float sc  = tanhf(sdiag[local]);
        const int row   = g * KP + tid;
        g_perm[row]    = node;
        g_score[row]   = sc;
        g_nodemap[node] = row;
        out[offBatch + row] = (float)g;
        out[offPerm  + row] = (float)node;
        out[offScore + row] = sc;
    }
}

// ---------------------------------------------------------------------------
// Kernel 2: x_new[row] = x[perm[row]] * score[row]   (one warp per row, float4)
// grid = NK/8 blocks of 256 threads (8 warps/block).
// ---------------------------------------------------------------------------
__global__ __launch_bounds__(256)
void gather_kernel(const float* __restrict__ x, float* __restrict__ out)
{
    const int row  = blockIdx.x * 8 + (threadIdx.x >> 5);
    const int lane = threadIdx.x & 31;
    const int src  = g_perm[row];
    const float sc = g_score[row];
    float4 v = ((const float4*)x)[(size_t)src * (FD / 4) + lane];
    v.x *= sc; v.y *= sc; v.z *= sc; v.w *= sc;
    ((float4*)out)[(size_t)row * (FD / 4) + lane] = v;
}

// ---------------------------------------------------------------------------
// Kernel 3: edge remap. row/col -> node_map lookup; invalid edges -> -1 / 0.
// Output sections written as float32.
// ---------------------------------------------------------------------------
__global__ __launch_bounds__(256)
void edge_kernel(const int* __restrict__ ei, const float* __restrict__ ew,
                 float* __restrict__ out, int E, int offEI, int offEW)
{
    const int e = blockIdx.x * blockDim.x + threadIdx.x;
    if (e >= E) return;
    const int r = g_nodemap[ei[e]];
    const int c = g_nodemap[ei[E + e]];
    const bool ok = (r >= 0) & (c >= 0);
    out[offEI + e]     = ok ? (float)r : -1.0f;
    out[offEI + E + e] = ok ? (float)c : -1.0f;
    out[offEW + e]     = ok ? ew[e] : 0.0f;
}

// ---------------------------------------------------------------------------
// Launch. Inputs (metadata order): x[N,F] f32, UM[N,N] f32, edge_index[2,E] i32,
// edge_weight[E] f32, batch[N] i32.
// Output: concat of flattened (x_new, new_edge_index, new_edge_weight,
//         batch_new, perm, score_perm) as float32.
// ---------------------------------------------------------------------------
extern "C" void kernel_launch(void* const* d_in, const int* in_sizes, int n_in,
                              void* d_out, int out_size)
{
    const float* x  = (const float*)d_in[0];
    const float* UM = (const float*)d_in[1];
    const int*   ei = (const int*)d_in[2];
    const float* ew = (const float*)d_in[3];
    float* out = (float*)d_out;

    const int E = in_sizes[3];                 // edge_weight element count

    const int offX     = 0;
    const int offEI    = offX  + NK * FD;      // 1048576
    const int offEW    = offEI + 2 * E;        // 1572864
    const int offBatch = offEW + E;            // 1835008
    const int offPerm  = offBatch + NK;        // 1843200
    const int offScore = offPerm + NK;         // 1851392

    topk_kernel<<<NB, 1024>>>(UM, out, offBatch, offPerm, offScore);
    gather_kernel<<<NK / 8, 256>>>(x, out + offX);
    edge_kernel<<<(E + 255) / 256, 256>>>(ei, ew, out, E, offEI, offEW);
}

// round 3
// speedup vs baseline: 1.0479x; 1.0479x over previous
#include <cuda_runtime.h>

// Fixed problem shape (PANUMPooling_8787503088315)
#define NB   8        // graphs
#define NPG  2048     // nodes per graph
#define KP   1024     // kept per graph
#define FD   128      // feature dim
#define NTOT (NB * NPG)   // 16384 total nodes
#define NK   (NB * KP)    // 8192 kept nodes

// Scratch (device globals: no allocation allowed)
__device__ int   g_perm[NK];
__device__ float g_score[NK];
__device__ int   g_nodemap[NTOT];

static __device__ __forceinline__ unsigned long long umax64(unsigned long long a, unsigned long long b) { return a > b ? a : b; }
static __device__ __forceinline__ unsigned long long umin64(unsigned long long a, unsigned long long b) { return a < b ? a : b; }

// ---------------------------------------------------------------------------
// Kernel 1: per-graph score + stable top-K. Register-resident bitonic sort:
// thread t owns elements 2t, 2t+1 (u64 keys). Key = [mono(diag):32][NPG-1-i:32]
// sorted DESCENDING => stable argsort(-score) order (ties -> lower idx first).
//   j==1            : intra-thread compare            (no smem, no sync)
//   j in [2,32]     : shfl.xor partner t^(j/2)        (no smem, no sync)
//   j in [64,1024]  : ping-pong SMEM exchange, 1 __syncthreads per stage
// 51/66 stages run entirely in registers.
// ---------------------------------------------------------------------------
__global__ __launch_bounds__(1024, 1)
void topk_kernel(const float* __restrict__ UM, float* __restrict__ out,
                 int offBatch, int offPerm, int offScore)
{
    __shared__ ulonglong2 bufA[1024];
    __shared__ ulonglong2 bufB[1024];

    const int g    = blockIdx.x;
    const int tid  = threadIdx.x;
    const int base = g * NPG;
    const int e0   = 2 * tid;        // first owned element index

    // Load two diagonal entries, build keys, init node_map for owned slots.
    unsigned long long k0, k1;
    {
        const int n0 = base + e0;
        const int n1 = n0 + 1;
        const float d0 = UM[(size_t)n0 * NTOT + n0];
        const float d1 = UM[(size_t)n1 * NTOT + n1];
        unsigned int b0 = __float_as_uint(d0);
        unsigned int b1 = __float_as_uint(d1);
        unsigned int m0 = (b0 & 0x80000000u) ? ~b0 : (b0 | 0x80000000u);
        unsigned int m1 = (b1 & 0x80000000u) ? ~b1 : (b1 | 0x80000000u);
        k0 = ((unsigned long long)m0 << 32) | (unsigned int)(NPG - 1 - e0);
        k1 = ((unsigned long long)m1 << 32) | (unsigned int)(NPG - 1 - (e0 + 1));
        g_nodemap[n0] = -1;
        g_nodemap[n1] = -1;
    }

    // Bitonic sort, descending.
    bool useA = true;
    for (int k = 2; k <= NPG; k <<= 1) {
        const bool bigFirst = ((e0 & k) == 0);   // same for e0 and e0+1 when k>=4; for k=2 only j=1 runs

        // ---- cross-warp stages: j >= 64 (thread-offset >= 32) ----
        for (int j = k >> 1; j >= 64; j >>= 1) {
            ulonglong2* wbuf = useA ? bufA : bufB;
            wbuf[tid] = make_ulonglong2(k0, k1);
            __syncthreads();
            const int q = tid ^ (j >> 1);
            const ulonglong2 r = wbuf[q];
            const bool low = ((tid & (j >> 1)) == 0);
            const bool keepMax = (low == bigFirst);
            k0 = keepMax ? umax64(k0, r.x) : umin64(k0, r.x);
            k1 = keepMax ? umax64(k1, r.y) : umin64(k1, r.y);
            useA = !useA;
        }

        // ---- warp-local shfl stages: j in [2, 32] ----
        for (int j = (k >> 1 < 32 ? k >> 1 : 32); j >= 2; j >>= 1) {
            const int half = j >> 1;
            const unsigned long long r0 = __shfl_xor_sync(0xFFFFFFFFu, k0, half);
            const unsigned long long r1 = __shfl_xor_sync(0xFFFFFFFFu, k1, half);
            const bool low = ((tid & half) == 0);
            const bool keepMax = (low == bigFirst);
            k0 = keepMax ? umax64(k0, r0) : umin64(k0, r0);
            k1 = keepMax ? umax64(k1, r1) : umin64(k1, r1);
        }

        // ---- j == 1: intra-thread ----
        {
            const bool bf1 = ((e0 & k) == 0);
            if (bf1 ? (k0 < k1) : (k0 > k1)) { unsigned long long t = k0; k0 = k1; k1 = t; }
        }
    }
    __syncthreads();   // node_map -1 init (and sort) complete before winners overwrite

    // Emit top-K: thread t < 512 holds ranks 2t and 2t+1.
    if (tid < KP / 2) {
        #pragma unroll
        for (int s = 0; s < 2; s++) {
            const unsigned long long key = s ? k1 : k0;
            const int rank  = e0 + s;
            const int local = NPG - 1 - (int)(key & 0xFFFFFFFFu);
            const int node  = base + local;
            const unsigned int mono = (unsigned int)(key >> 32);
            const unsigned int bits = (mono & 0x80000000u) ? (mono & 0x7FFFFFFFu) : ~mono;
            const float sc = tanhf(__uint_as_float(bits));
            const int row  = g * KP + rank;
            g_perm[row]     = node;
            g_score[row]    = sc;
            g_nodemap[node] = row;
            out[offBatch + row] = (float)g;
            out[offPerm  + row] = (float)node;
            out[offScore + row] = sc;
        }
    }
}

// ---------------------------------------------------------------------------
// Kernel 2: x_new[row] = x[perm[row]] * score[row]   (one warp per row, float4)
// ---------------------------------------------------------------------------
__global__ __launch_bounds__(256)
void gather_kernel(const float* __restrict__ x, float* __restrict__ out)
{
    const int row  = blockIdx.x * 8 + (threadIdx.x >> 5);
    const int lane = threadIdx.x & 31;
    const int src  = g_perm[row];
    const float sc = g_score[row];
    float4 v = ((const float4*)x)[(size_t)src * (FD / 4) + lane];
    v.x *= sc; v.y *= sc; v.z *= sc; v.w *= sc;
    ((float4*)out)[(size_t)row * (FD / 4) + lane] = v;
}

// ---------------------------------------------------------------------------
// Kernel 3: edge remap, 4 edges per thread (vectorized loads/stores).
// row/col -> node_map lookup; invalid edges -> -1 / 0.
// E, offEI, offEW are all multiples of 4.
// ---------------------------------------------------------------------------
__global__ __launch_bounds__(256)
void edge_kernel(const int* __restrict__ ei, const float* __restrict__ ew,
                 float* __restrict__ out, int E, int offEI, int offEW)
{
    const int e4 = blockIdx.x * blockDim.x + threadIdx.x;   // edge group of 4
    if (e4 >= E / 4) return;

    const int4   rsrc = ((const int4*)ei)[e4];
    const int4   csrc = ((const int4*)(ei + E))[e4];
    const float4 w    = ((const float4*)ew)[e4];

    int   r[4] = { g_nodemap[rsrc.x], g_nodemap[rsrc.y], g_nodemap[rsrc.z], g_nodemap[rsrc.w] };
    int   c[4] = { g_nodemap[csrc.x], g_nodemap[csrc.y], g_nodemap[csrc.z], g_nodemap[csrc.w] };
    float wv[4] = { w.x, w.y, w.z, w.w };

    float ro[4], co[4], wo[4];
    #pragma unroll
    for (int s = 0; s < 4; s++) {
        const bool ok = (r[s] >= 0) & (c[s] >= 0);
        ro[s] = ok ? (float)r[s] : -1.0f;
        co[s] = ok ? (float)c[s] : -1.0f;
        wo[s] = ok ? wv[s] : 0.0f;
    }
    ((float4*)(out + offEI))[e4]     = make_float4(ro[0], ro[1], ro[2], ro[3]);
    ((float4*)(out + offEI + E))[e4] = make_float4(co[0], co[1], co[2], co[3]);
    ((float4*)(out + offEW))[e4]     = make_float4(wo[0], wo[1], wo[2], wo[3]);
}

// ---------------------------------------------------------------------------
// Launch. Inputs (metadata order): x[N,F] f32, UM[N,N] f32, edge_index[2,E] i32,
// edge_weight[E] f32, batch[N] i32.
// Output: concat of flattened (x_new, new_edge_index, new_edge_weight,
//         batch_new, perm, score_perm) as float32.
// ---------------------------------------------------------------------------
extern "C" void kernel_launch(void* const* d_in, const int* in_sizes, int n_in,
                              void* d_out, int out_size)
{
    const float* x  = (const float*)d_in[0];
    const float* UM = (const float*)d_in[1];
    const int*   ei = (const int*)d_in[2];
    const float* ew = (const float*)d_in[3];
    float* out = (float*)d_out;

    const int E = in_sizes[3];                 // edge_weight element count

    const int offX     = 0;
    const int offEI    = offX  + NK * FD;      // 1048576
    const int offEW    = offEI + 2 * E;        // 1572864
    const int offBatch = offEW + E;            // 1835008
    const int offPerm  = offBatch + NK;        // 1843200
    const int offScore = offPerm + NK;         // 1851392

    topk_kernel<<<NB, 1024>>>(UM, out, offBatch, offPerm, offScore);
    gather_kernel<<<NK / 8, 256>>>(x, out + offX);
    edge_kernel<<<(E / 4 + 255) / 256, 256>>>(ei, ew, out, E, offEI, offEW);
}